// round 14
// baseline (speedup 1.0000x reference)
#include <cuda_runtime.h>
#include <cuda_bf16.h>
#include <cuda_fp16.h>
#include <cstdint>

// Problem constants (fixed shapes)
#define NTOK  4096      // B*S = 2*2048
#define DDIM  1024
#define WDIM  4096
#define SLOT  8
#define NLEAF 8         // 1 << TREE_DEPTH
#define NC    11        // SLOT + 3

// GEMM tiling: CTA 128(M) x 256(N), K-chunk 64, 512 threads (16 warps, 4x4)
#define TMM 128
#define TNN 256
#define KCC 64
#define GT  512
#define ABYTES (TMM * 128)            // 16 KB  (128 rows x 128B)
#define BBYTES (TNN * 128)            // 32 KB
#define OFF_A  0
#define OFF_B  (ABYTES)
#define STAGE  (ABYTES + BBYTES)      // 49152
#define NSTG   3
#define GSMEM  (NSTG * STAGE)         // 147456
#define NCH    (WDIM / KCC)           // 64

// wsel row layout per w (floats): [8 leaves x 16 dup weights][8 leaves x 2 dup bias]
#define WSEL_ROW 144

// Scratch (static device arrays — runtime alloc is forbidden)
__device__ __align__(128) float  g_wsel [(size_t)WDIM * WSEL_ROW];
__device__ __align__(128) float  g_slots[NTOK * SLOT];
__device__ __align__(128) __half g_a[(size_t)NTOK * WDIM];   // roots, fp16, [M][K]
__device__ __align__(128) __half g_b[(size_t)DDIM * WDIM];   // out_w^T, fp16, [N][K]

// ---------------------------------------------------------------------------
// PTX helpers
// ---------------------------------------------------------------------------
__device__ __forceinline__ uint32_t smem_u32(const void* p) {
    uint32_t a;
    asm("{ .reg .u64 t; cvta.to.shared.u64 t, %1; cvt.u32.u64 %0, t; }"
        : "=r"(a) : "l"(p));
    return a;
}

__device__ __forceinline__ void cp16(uint32_t saddr, const void* g) {
    asm volatile("cp.async.cg.shared.global [%0], [%1], 16;"
                 :: "r"(saddr), "l"(g) : "memory");
}
#define CP_COMMIT() asm volatile("cp.async.commit_group;" ::: "memory")
#define CP_WAIT(n)  asm volatile("cp.async.wait_group %0;" :: "n"(n) : "memory")

__device__ __forceinline__ void ldsm_x4(uint32_t* r, uint32_t addr) {
    asm volatile("ldmatrix.sync.aligned.m8n8.x4.shared.b16 {%0,%1,%2,%3}, [%4];"
                 : "=r"(r[0]), "=r"(r[1]), "=r"(r[2]), "=r"(r[3]) : "r"(addr));
}

__device__ __forceinline__ void mma_fp16(float* c, const uint32_t* a,
                                         uint32_t b0, uint32_t b1) {
    asm volatile(
        "mma.sync.aligned.m16n8k16.row.col.f32.f16.f16.f32 "
        "{%0,%1,%2,%3}, {%4,%5,%6,%7}, {%8,%9}, {%0,%1,%2,%3};"
        : "+f"(c[0]), "+f"(c[1]), "+f"(c[2]), "+f"(c[3])
        : "r"(a[0]), "r"(a[1]), "r"(a[2]), "r"(a[3]), "r"(b0), "r"(b1));
}

// --- packed f32x2 ops (base sm_100+ PTX; FFMA2/FMUL2 in SASS) ---
__device__ __forceinline__ uint64_t fma2(uint64_t a, uint64_t b, uint64_t c) {
    uint64_t d;
    asm("fma.rn.f32x2 %0, %1, %2, %3;" : "=l"(d) : "l"(a), "l"(b), "l"(c));
    return d;
}
__device__ __forceinline__ uint64_t mul2(uint64_t a, uint64_t b) {
    uint64_t d;
    asm("mul.rn.f32x2 %0, %1, %2;" : "=l"(d) : "l"(a), "l"(b));
    return d;
}
__device__ __forceinline__ uint64_t pack2(float lo, float hi) {
    uint64_t d;
    asm("mov.b64 %0, {%1, %2};" : "=l"(d) : "f"(lo), "f"(hi));
    return d;
}
__device__ __forceinline__ void unpack2(float& lo, float& hi, uint64_t v) {
    asm("mov.b64 {%0, %1}, %2;" : "=f"(lo), "=f"(hi) : "l"(v));
}

// Accurate fast tanh: tanh(x) = 1 - 2/(exp(2x)+1)
__device__ __forceinline__ float tanh_fast(float x) {
    float e = __expf(2.0f * x);
    return 1.0f - __fdividef(2.0f, e + 1.0f);
}

// packed tanh of pre-scaled args z' = 2*log2(e)*z (scalar MUFU per half)
__device__ __forceinline__ uint64_t tanh2_prescaled(uint64_t z2) {
    float za, zb;
    unpack2(za, zb, z2);
    float ea, eb, ra, rb;
    asm("ex2.approx.f32 %0, %1;" : "=f"(ea) : "f"(za));
    asm("ex2.approx.f32 %0, %1;" : "=f"(eb) : "f"(zb));
    asm("rcp.approx.f32 %0, %1;" : "=f"(ra) : "f"(ea + 1.0f));
    asm("rcp.approx.f32 %0, %1;" : "=f"(rb) : "f"(eb + 1.0f));
    return pack2(fmaf(-2.0f, ra, 1.0f), fmaf(-2.0f, rb, 1.0f));
}

// ---------------------------------------------------------------------------
// Kernel 1: selector softmax + constant folding; duplicated-weight layout.
// Row per w (144 floats): leaf l weights duplicated at [l*16 + 2c {, +1}],
// leaf l bias duplicated at [128 + l*2 {, +1}].
// ---------------------------------------------------------------------------
__global__ __launch_bounds__(256)
void prep_selector_kernel(const float* __restrict__ leaf_logits,
                          float* __restrict__ wsel) {
    int idx = blockIdx.x * blockDim.x + threadIdx.x;   // w*8 + leaf
    if (idx >= WDIM * NLEAF) return;
    const float* lg = leaf_logits + (size_t)idx * NC;

    float m = lg[0];
    #pragma unroll
    for (int c = 1; c < NC; c++) m = fmaxf(m, lg[c]);

    float e[NC];
    float s = 0.0f;
    #pragma unroll
    for (int c = 0; c < NC; c++) { e[c] = __expf(lg[c] - m); s += e[c]; }
    float inv = 1.0f / s;

    int w = idx >> 3, leaf = idx & 7;
    float* o = wsel + (size_t)w * WSEL_ROW + leaf * 16;
    #pragma unroll
    for (int c = 0; c < SLOT; c++) {
        float v = e[c] * inv;
        o[2 * c] = v;
        o[2 * c + 1] = v;
    }
    float bias = (e[10] - e[8]) * inv;   // folded constants [-1, 0, 1]
    float* ob = wsel + (size_t)w * WSEL_ROW + 128 + leaf * 2;
    ob[0] = bias;
    ob[1] = bias;
}

// ---------------------------------------------------------------------------
// Kernel 2: slots = tanh(hidden @ slot_w + slot_b).  One warp per token.
// ---------------------------------------------------------------------------
__global__ __launch_bounds__(256)
void slots_kernel(const float* __restrict__ hidden,
                  const float* __restrict__ slot_w,
                  const float* __restrict__ slot_b,
                  float* __restrict__ slots) {
    int warp = (blockIdx.x * blockDim.x + threadIdx.x) >> 5;
    int lane = threadIdx.x & 31;
    if (warp >= NTOK) return;

    const float* h = hidden + (size_t)warp * DDIM;
    float acc[SLOT];
    #pragma unroll
    for (int s = 0; s < SLOT; s++) acc[s] = 0.0f;

    for (int j = lane; j < DDIM; j += 32) {
        float hv = h[j];
        float4 w0 = *reinterpret_cast<const float4*>(slot_w + (size_t)j * SLOT);
        float4 w1 = *reinterpret_cast<const float4*>(slot_w + (size_t)j * SLOT + 4);
        acc[0] = fmaf(hv, w0.x, acc[0]);
        acc[1] = fmaf(hv, w0.y, acc[1]);
        acc[2] = fmaf(hv, w0.z, acc[2]);
        acc[3] = fmaf(hv, w0.w, acc[3]);
        acc[4] = fmaf(hv, w1.x, acc[4]);
        acc[5] = fmaf(hv, w1.y, acc[5]);
        acc[6] = fmaf(hv, w1.z, acc[6]);
        acc[7] = fmaf(hv, w1.w, acc[7]);
    }
    #pragma unroll
    for (int off = 16; off > 0; off >>= 1) {
        #pragma unroll
        for (int s = 0; s < SLOT; s++)
            acc[s] += __shfl_down_sync(0xffffffffu, acc[s], off);
    }
    if (lane == 0) {
        #pragma unroll
        for (int s = 0; s < SLOT; s++)
            slots[(size_t)warp * SLOT + s] = tanh_fast(acc[s] + slot_b[s]);
    }
}

// ---------------------------------------------------------------------------
// Kernel 3: roots -> fp16, [token][w] row-major.  Packed f32x2 math:
// lane = token pair (t, t+32) packed {lo,hi}; weights pre-duplicated in smem
// so every FMA is one FFMA2 on broadcast operands. Output staged in smem
// (66-half rows: conflict-free STS.16), flushed via 4x LDS.32 + STG.128.
// ---------------------------------------------------------------------------
#define RW   64     // w per CTA
#define RT   256    // tokens per CTA
#define ROW_H 66    // s_out row stride in halves (33 words -> conflict-free STS.16)
__global__ __launch_bounds__(256)
void roots_kernel(const float* __restrict__ wsel,
                  const float* __restrict__ slots,
                  const float* __restrict__ np,
                  __half* __restrict__ A) {
    __shared__ __align__(16) float  s_wsel[RW * WSEL_ROW];       // 36864 B
    __shared__ __align__(16) __half s_out[64 * ROW_H];           //  8448 B

    const int tid  = threadIdx.x;
    const int lane = tid & 31;
    const int wrp  = tid >> 5;            // 0..7
    const int w0   = blockIdx.x * RW;
    const int tb0  = blockIdx.y * RT;

    // load wsel tile once: 64 rows x 144 floats = 2304 float4 (contiguous)
    {
        const float4* gw = reinterpret_cast<const float4*>(wsel + (size_t)w0 * WSEL_ROW);
        float4* sw = reinterpret_cast<float4*>(s_wsel);
        #pragma unroll
        for (int i = 0; i < 9; i++) sw[tid + i * 256] = gw[tid + i * 256];
    }

    // node coefficients, pre-scaled by 2*log2(e) (folds tanh's exp scaling)
    const float SC  = 2.8853900817779268f;
    const float a1  = (np[0] + np[3]) * SC;   // (lw + dw)
    const float a2  = (np[1] - np[3]) * SC;   // (rw - dw)
    const float pws = np[2] * SC;
    const float nbs = np[4] * SC;
    const uint64_t a12 = pack2(a1, a1);
    const uint64_t a22 = pack2(a2, a2);
    const uint64_t pw2 = pack2(pws, pws);
    const uint64_t nb2 = pack2(nbs, nbs);
    __syncthreads();

    for (int tt = 0; tt < RT / 64; tt++) {
        const int tokA = tb0 + tt * 64 + lane;        // token A (lo half)
        const int tokB = tokA + 32;                   // token B (hi half)

        // pack both tokens' slots once per tt
        uint64_t sl2[SLOT];
        {
            float4 s0 = __ldg(reinterpret_cast<const float4*>(slots + (size_t)tokA * SLOT));
            float4 s1 = __ldg(reinterpret_cast<const float4*>(slots + (size_t)tokA * SLOT + 4));
            float4 t0 = __ldg(reinterpret_cast<const float4*>(slots + (size_t)tokB * SLOT));
            float4 t1 = __ldg(reinterpret_cast<const float4*>(slots + (size_t)tokB * SLOT + 4));
            sl2[0] = pack2(s0.x, t0.x); sl2[1] = pack2(s0.y, t0.y);
            sl2[2] = pack2(s0.z, t0.z); sl2[3] = pack2(s0.w, t0.w);
            sl2[4] = pack2(s1.x, t1.x); sl2[5] = pack2(s1.y, t1.y);
            sl2[6] = pack2(s1.z, t1.z); sl2[7] = pack2(s1.w, t1.w);
        }

        #pragma unroll 2
        for (int wi = 0; wi < RW / 8; wi++) {
            const int wl = wrp * 8 + wi;                 // local w index (warp-uniform)
            const float* wp = &s_wsel[wl * WSEL_ROW];

            uint64_t v2[NLEAF];
            #pragma unroll
            for (int l = 0; l < NLEAF; l++) {
                const ulonglong2* q =
                    reinterpret_cast<const ulonglong2*>(wp + l * 16);
                ulonglong2 p0 = q[0];     // {w0,w0},{w1,w1}
                ulonglong2 p1 = q[1];
                ulonglong2 p2 = q[2];
                ulonglong2 p3 = q[3];
                uint64_t b2 = *reinterpret_cast<const uint64_t*>(wp + 128 + l * 2);
                uint64_t a = fma2(p0.x, sl2[0], b2);
                a = fma2(p0.y, sl2[1], a);
                a = fma2(p1.x, sl2[2], a);
                a = fma2(p1.y, sl2[3], a);
                a = fma2(p2.x, sl2[4], a);
                a = fma2(p2.y, sl2[5], a);
                a = fma2(p3.x, sl2[6], a);
                a = fma2(p3.y, sl2[7], a);
                v2[l] = a;
            }

            // 3-level tree, fully packed: node = tanh(a1*L + a2*R + pw*L*R + nb)
            #pragma unroll
            for (int n = 4; n >= 1; n >>= 1) {
                #pragma unroll
                for (int j = 0; j < 4; j++) {
                    if (j < n) {
                        uint64_t L2 = v2[2 * j], R2 = v2[2 * j + 1];
                        uint64_t z = fma2(pw2, mul2(L2, R2), nb2);
                        z = fma2(a22, R2, z);
                        z = fma2(a12, L2, z);
                        v2[j] = tanh2_prescaled(z);
                    }
                }
            }
            float rA, rB;
            unpack2(rA, rB, v2[0]);
            s_out[lane * ROW_H + wl]        = __float2half(rA);
            s_out[(lane + 32) * ROW_H + wl] = __float2half(rB);
        }
        __syncthreads();

        // flush: 64 rows x 64 halves (128B) coalesced.
        // Row byte stride = 132 (4B-aligned only) -> gather via 4x LDS.32.
        {
            const uint32_t* sp = reinterpret_cast<const uint32_t*>(s_out);
            #pragma unroll
            for (int f = 0; f < 2; f++) {
                int idx = tid + f * 256;             // 0..511
                int row = idx >> 3;                  // 0..63
                int seg = idx & 7;                   // 0..7 (x16 bytes)
                int e = row * 33 + seg * 4;          // word index (132B row = 33 words)
                uint4 val;
                val.x = sp[e + 0];
                val.y = sp[e + 1];
                val.z = sp[e + 2];
                val.w = sp[e + 3];
                *reinterpret_cast<uint4*>(A + (size_t)(tb0 + tt * 64 + row) * WDIM + w0 + seg * 8) = val;
            }
        }
        __syncthreads();
    }
}

// ---------------------------------------------------------------------------
// Kernel 3b: transpose out_w [K][N] fp32 -> B [N][K] fp16
// ---------------------------------------------------------------------------
__global__ __launch_bounds__(256)
void transpose_kernel(const float* __restrict__ W,
                      __half* __restrict__ B) {
    __shared__ float t[32][33];
    int tx = threadIdx.x, ty = threadIdx.y;       // block (32, 8)
    int k0 = blockIdx.x * 32, n0 = blockIdx.y * 32;

    #pragma unroll
    for (int i = 0; i < 4; i++)
        t[ty + 8 * i][tx] = W[(size_t)(k0 + ty + 8 * i) * DDIM + n0 + tx];
    __syncthreads();

    #pragma unroll
    for (int i = 0; i < 4; i++)
        B[(size_t)(n0 + ty + 8 * i) * WDIM + k0 + tx] = __float2half(t[tx][ty + 8 * i]);
}

// ---------------------------------------------------------------------------
// Kernel 4: mma.sync fp16 GEMM.  C[4096,1024] = A B^T + bias  (fp32 accum)
// CTA 128x256, K-chunk 64, 3-stage cp.async pipeline, 16 warps (4x4).
// ---------------------------------------------------------------------------
__global__ void __launch_bounds__(GT, 1)
gemm_mma_kernel(const __half* __restrict__ A,
                const __half* __restrict__ B,
                const float* __restrict__ bias,
                float* __restrict__ C) {
    extern __shared__ char smem[];
    const uint32_t sbase = smem_u32(smem);
    const int tid  = threadIdx.x;
    const int lane = tid & 31;
    const int w    = tid >> 5;        // 0..15
    const int wm   = w & 3;           // M warp coord (x32)
    const int wn   = w >> 2;          // N warp coord (x64)
    const int brow = blockIdx.y * TMM;
    const int bcol = blockIdx.x * TNN;
    const int K = WDIM;

    float acc[2][8][4];
    #pragma unroll
    for (int a = 0; a < 2; a++)
        #pragma unroll
        for (int b = 0; b < 8; b++)
            #pragma unroll
            for (int c = 0; c < 4; c++) acc[a][b][c] = 0.0f;

    // ldmatrix lane->address precomputation
    const int lr   = lane & 7;
    const int ls8  = (lane >> 3) & 1;       // A: +8 rows    B: +1 k-chunk
    const int lhi  = lane >> 4;             // A: +1 k-chunk B: +8 rows
    const int arow0 = wm * 32 + lr + ls8 * 8;
    const int brow0 = wn * 64 + lr + lhi * 8;
    const uint32_t aswz = arow0 & 7;
    const uint32_t bswz = brow0 & 7;
    uint32_t arowb[2], browb[4];
    #pragma unroll
    for (int mt = 0; mt < 2; mt++) arowb[mt] = (uint32_t)(arow0 + mt * 16) << 7;
    #pragma unroll
    for (int i = 0; i < 4; i++)    browb[i] = (uint32_t)(brow0 + i * 16) << 7;

    // stage loader: A rows (brow..+127), B rows (bcol..+255), k0..k0+63
    auto load_stage = [&](int ci) {
        const uint32_t sb = sbase + (ci % NSTG) * STAGE;
        const int k0 = ci * KCC;
        #pragma unroll
        for (int it = 0; it < 2; it++) {
            int idx = tid + it * GT;          // 0..1023
            int r = idx >> 3, c = idx & 7;
            uint32_t sw = ((uint32_t)r << 7) + (((uint32_t)(c ^ (r & 7))) << 4);
            cp16(sb + OFF_A + sw, A + (size_t)(brow + r) * K + k0 + c * 8);
        }
        #pragma unroll
        for (int it = 0; it < 4; it++) {
            int idx = tid + it * GT;          // 0..2047
            int r = idx >> 3, c = idx & 7;
            uint32_t sw = ((uint32_t)r << 7) + (((uint32_t)(c ^ (r & 7))) << 4);
            cp16(sb + OFF_B + sw, B + (size_t)(bcol + r) * K + k0 + c * 8);
        }
    };

    load_stage(0); CP_COMMIT();
    load_stage(1); CP_COMMIT();

    for (int i = 0; i < NCH; i++) {
        CP_WAIT(1);            // stage i landed (this thread's view)
        __syncthreads();       // visible to all; all warps done with stage i-1

        if (i + 2 < NCH) { load_stage(i + 2); CP_COMMIT(); }

        const uint32_t sb = sbase + (i % NSTG) * STAGE;
        #pragma unroll
        for (int s = 0; s < 4; s++) {
            uint32_t ach = (((uint32_t)(2 * s + lhi)) ^ aswz) << 4;
            uint32_t bch = (((uint32_t)(2 * s + ls8)) ^ bswz) << 4;
            uint32_t af[2][4], bf[4][4];
            #pragma unroll
            for (int mt = 0; mt < 2; mt++)
                ldsm_x4(af[mt], sb + OFF_A + arowb[mt] + ach);
            #pragma unroll
            for (int bt = 0; bt < 4; bt++)
                ldsm_x4(bf[bt], sb + OFF_B + browb[bt] + bch);
            #pragma unroll
            for (int mt = 0; mt < 2; mt++)
                #pragma unroll
                for (int bt = 0; bt < 4; bt++) {
                    mma_fp16(acc[mt][2 * bt + 0], af[mt], bf[bt][0], bf[bt][1]);
                    mma_fp16(acc[mt][2 * bt + 1], af[mt], bf[bt][2], bf[bt][3]);
                }
        }
    }

    // Epilogue: acc -> C + bias
    const int r0 = lane >> 2;
    const int c0 = (lane & 3) * 2;
    #pragma unroll
    for (int mt = 0; mt < 2; mt++) {
        int grow = brow + wm * 32 + mt * 16 + r0;
        #pragma unroll
        for (int half = 0; half < 2; half++) {
            float* crow = C + (size_t)(grow + half * 8) * DDIM;
            #pragma unroll
            for (int nt = 0; nt < 8; nt++) {
                int gc = bcol + wn * 64 + nt * 8 + c0;
                float2 o;
                o.x = acc[mt][nt][half * 2 + 0] + bias[gc];
                o.y = acc[mt][nt][half * 2 + 1] + bias[gc + 1];
                *reinterpret_cast<float2*>(crow + gc) = o;
            }
        }
    }
}

// ---------------------------------------------------------------------------
// Launch.  Inputs: hidden, slot_w, slot_b, leaf_logits, node_params, out_w, out_b
// ---------------------------------------------------------------------------
extern "C" void kernel_launch(void* const* d_in, const int* in_sizes, int n_in,
                              void* d_out, int out_size) {
    const float* hidden      = (const float*)d_in[0];
    const float* slot_w      = (const float*)d_in[1];
    const float* slot_b      = (const float*)d_in[2];
    const float* leaf_logits = (const float*)d_in[3];
    const float* node_params = (const float*)d_in[4];
    const float* out_w       = (const float*)d_in[5];
    const float* out_b       = (const float*)d_in[6];
    float* out = (float*)d_out;

    float* wsel;  cudaGetSymbolAddress((void**)&wsel,  g_wsel);
    float* slots; cudaGetSymbolAddress((void**)&slots, g_slots);
    __half *A, *B;
    cudaGetSymbolAddress((void**)&A, g_a);
    cudaGetSymbolAddress((void**)&B, g_b);

    cudaFuncSetAttribute(gemm_mma_kernel,
                         cudaFuncAttributeMaxDynamicSharedMemorySize, GSMEM);

    // 1) selector softmax + constant folding (duplicated layout)
    prep_selector_kernel<<<(WDIM * NLEAF + 255) / 256, 256>>>(leaf_logits, wsel);

    // 2) slots
    slots_kernel<<<(NTOK * 32 + 255) / 256, 256>>>(hidden, slot_w, slot_b, slots);

    // 3b) transpose out_w -> fp16 [N][K]
    {
        dim3 grid(WDIM / 32, DDIM / 32);
        transpose_kernel<<<grid, dim3(32, 8)>>>(out_w, B);
    }

    // 3) roots -> fp16 [M][K]
    {
        dim3 grid(WDIM / RW, NTOK / RT);
        roots_kernel<<<grid, 256>>>(wsel, slots, node_params, A);
    }

    // 4) tensor-core GEMM + bias
    {
        dim3 grid(DDIM / TNN, NTOK / TMM);
        gemm_mma_kernel<<<grid, GT, GSMEM>>>(A, B, out_b, out);
    }
}

// round 15
// speedup vs baseline: 1.1490x; 1.1490x over previous
#include <cuda_runtime.h>
#include <cuda_bf16.h>
#include <cuda_fp16.h>
#include <cstdint>

// Problem constants (fixed shapes)
#define NTOK  4096      // B*S = 2*2048
#define DDIM  1024
#define WDIM  4096
#define SLOT  8
#define NLEAF 8         // 1 << TREE_DEPTH
#define NC    11        // SLOT + 3

// GEMM tiling: CTA 128(M) x 256(N), K-chunk 64, 512 threads (16 warps, 4x4)
#define TMM 128
#define TNN 256
#define KCC 64
#define GT  512
#define ABYTES (TMM * 128)            // 16 KB  (128 rows x 128B)
#define BBYTES (TNN * 128)            // 32 KB
#define OFF_A  0
#define OFF_B  (ABYTES)
#define STAGE  (ABYTES + BBYTES)      // 49152
#define NSTG   4
#define GSMEM  (NSTG * STAGE)         // 196608
#define NCH    (WDIM / KCC)           // 64

// Scratch (static device arrays — runtime alloc is forbidden)
__device__ __align__(128) float  g_wsel [WDIM * NLEAF * 12];  // 12-padded per leaf
__device__ __align__(128) float  g_slots[NTOK * SLOT];
__device__ __align__(128) __half g_a[(size_t)NTOK * WDIM];   // roots, fp16, [M][K]
__device__ __align__(128) __half g_b[(size_t)DDIM * WDIM];   // out_w^T, fp16, [N][K]

// ---------------------------------------------------------------------------
// PTX helpers (sm_80-era features only — no 'a'-suffix instructions)
// ---------------------------------------------------------------------------
__device__ __forceinline__ uint32_t smem_u32(const void* p) {
    uint32_t a;
    asm("{ .reg .u64 t; cvta.to.shared.u64 t, %1; cvt.u32.u64 %0, t; }"
        : "=r"(a) : "l"(p));
    return a;
}

__device__ __forceinline__ void cp16(uint32_t saddr, const void* g) {
    asm volatile("cp.async.cg.shared.global [%0], [%1], 16;"
                 :: "r"(saddr), "l"(g) : "memory");
}
#define CP_COMMIT() asm volatile("cp.async.commit_group;" ::: "memory")
#define CP_WAIT(n)  asm volatile("cp.async.wait_group %0;" :: "n"(n) : "memory")

__device__ __forceinline__ void ldsm_x4(uint32_t* r, uint32_t addr) {
    asm volatile("ldmatrix.sync.aligned.m8n8.x4.shared.b16 {%0,%1,%2,%3}, [%4];"
                 : "=r"(r[0]), "=r"(r[1]), "=r"(r[2]), "=r"(r[3]) : "r"(addr));
}

__device__ __forceinline__ void mma_fp16(float* c, const uint32_t* a,
                                         uint32_t b0, uint32_t b1) {
    asm volatile(
        "mma.sync.aligned.m16n8k16.row.col.f32.f16.f16.f32 "
        "{%0,%1,%2,%3}, {%4,%5,%6,%7}, {%8,%9}, {%0,%1,%2,%3};"
        : "+f"(c[0]), "+f"(c[1]), "+f"(c[2]), "+f"(c[3])
        : "r"(a[0]), "r"(a[1]), "r"(a[2]), "r"(a[3]), "r"(b0), "r"(b1));
}

// Accurate fast tanh: tanh(x) = 1 - 2/(exp(2x)+1)
__device__ __forceinline__ float tanh_fast(float x) {
    float e = __expf(2.0f * x);
    return 1.0f - __fdividef(2.0f, e + 1.0f);
}

// tanh from pre-scaled argument z' = 2*log2(e)*z : 4 instructions, 2 MUFU
__device__ __forceinline__ float tanh_prescaled(float zp) {
    float e, r;
    asm("ex2.approx.f32 %0, %1;" : "=f"(e) : "f"(zp));
    asm("rcp.approx.f32 %0, %1;" : "=f"(r) : "f"(e + 1.0f));
    return fmaf(-2.0f, r, 1.0f);
}

// ---------------------------------------------------------------------------
// Kernel 1: selector softmax + constant folding (12-padded output)
// ---------------------------------------------------------------------------
__global__ __launch_bounds__(256)
void prep_selector_kernel(const float* __restrict__ leaf_logits,
                          float* __restrict__ wsel) {
    int idx = blockIdx.x * blockDim.x + threadIdx.x;   // w*8 + leaf
    if (idx >= WDIM * NLEAF) return;
    const float* lg = leaf_logits + (size_t)idx * NC;

    float m = lg[0];
    #pragma unroll
    for (int c = 1; c < NC; c++) m = fmaxf(m, lg[c]);

    float e[NC];
    float s = 0.0f;
    #pragma unroll
    for (int c = 0; c < NC; c++) { e[c] = __expf(lg[c] - m); s += e[c]; }
    float inv = 1.0f / s;

    float* o = wsel + (size_t)idx * 12;
    #pragma unroll
    for (int c = 0; c < SLOT; c++) o[c] = e[c] * inv;
    o[8]  = (e[10] - e[8]) * inv;   // folded constants [-1, 0, 1]
    o[9]  = 0.0f;
    o[10] = 0.0f;
    o[11] = 0.0f;
}

// ---------------------------------------------------------------------------
// Kernel 2: slots = tanh(hidden @ slot_w + slot_b).  One warp per token.
// ---------------------------------------------------------------------------
__global__ __launch_bounds__(256)
void slots_kernel(const float* __restrict__ hidden,
                  const float* __restrict__ slot_w,
                  const float* __restrict__ slot_b,
                  float* __restrict__ slots) {
    int warp = (blockIdx.x * blockDim.x + threadIdx.x) >> 5;
    int lane = threadIdx.x & 31;
    if (warp >= NTOK) return;

    const float* h = hidden + (size_t)warp * DDIM;
    float acc[SLOT];
    #pragma unroll
    for (int s = 0; s < SLOT; s++) acc[s] = 0.0f;

    for (int j = lane; j < DDIM; j += 32) {
        float hv = h[j];
        float4 w0 = *reinterpret_cast<const float4*>(slot_w + (size_t)j * SLOT);
        float4 w1 = *reinterpret_cast<const float4*>(slot_w + (size_t)j * SLOT + 4);
        acc[0] = fmaf(hv, w0.x, acc[0]);
        acc[1] = fmaf(hv, w0.y, acc[1]);
        acc[2] = fmaf(hv, w0.z, acc[2]);
        acc[3] = fmaf(hv, w0.w, acc[3]);
        acc[4] = fmaf(hv, w1.x, acc[4]);
        acc[5] = fmaf(hv, w1.y, acc[5]);
        acc[6] = fmaf(hv, w1.z, acc[6]);
        acc[7] = fmaf(hv, w1.w, acc[7]);
    }
    #pragma unroll
    for (int off = 16; off > 0; off >>= 1) {
        #pragma unroll
        for (int s = 0; s < SLOT; s++)
            acc[s] += __shfl_down_sync(0xffffffffu, acc[s], off);
    }
    if (lane == 0) {
        #pragma unroll
        for (int s = 0; s < SLOT; s++)
            slots[(size_t)warp * SLOT + s] = tanh_fast(acc[s] + slot_b[s]);
    }
}

// ---------------------------------------------------------------------------
// Kernel 3: roots -> fp16, [token][w] row-major.
// CTA: 64 w x 256 tokens. lane = token; each lane handles tokens (t, t+32)
// so every leaf-weight broadcast LDS is amortized over 2 dot products.
// wsel reads are warp-uniform (broadcast LDS). Output staged in smem
// (66-half rows: conflict-free STS.16), flushed via 4x LDS.32 + STG.128.
// ---------------------------------------------------------------------------
#define RW   64     // w per CTA
#define RT   256    // tokens per CTA
#define ROW_H 66    // s_out row stride in halves (33 words -> conflict-free STS.16)
__global__ __launch_bounds__(256)
void roots_kernel(const float* __restrict__ wsel,
                  const float* __restrict__ slots,
                  const float* __restrict__ np,
                  __half* __restrict__ A) {
    __shared__ float  s_wsel[RW * 96];
    __shared__ __align__(16) __half s_out[64 * ROW_H];

    const int tid  = threadIdx.x;
    const int lane = tid & 31;
    const int wrp  = tid >> 5;            // 0..7
    const int w0   = blockIdx.x * RW;
    const int tb0  = blockIdx.y * RT;

    // load wsel tile once: 64 rows x 96 floats = 1536 float4
    {
        const float4* gw = reinterpret_cast<const float4*>(wsel + (size_t)w0 * 96);
        float4* sw = reinterpret_cast<float4*>(s_wsel);
        #pragma unroll
        for (int i = 0; i < 6; i++) sw[tid + i * 256] = gw[tid + i * 256];
    }

    // node coefficients, pre-scaled by 2*log2(e) (folds tanh's exp scaling)
    const float SC  = 2.8853900817779268f;
    const float a1  = (np[0] + np[3]) * SC;   // (lw + dw)
    const float a2  = (np[1] - np[3]) * SC;   // (rw - dw)
    const float pws = np[2] * SC;
    const float nbs = np[4] * SC;
    __syncthreads();

    for (int tt = 0; tt < RT / 64; tt++) {
        const int tokA = tb0 + tt * 64 + lane;        // token A
        const int tokB = tokA + 32;                   // token B

        // both tokens' slots (L1/L2-cached; reused by all w-tiles)
        float slA[SLOT], slB[SLOT];
        {
            float4 s0 = __ldg(reinterpret_cast<const float4*>(slots + (size_t)tokA * SLOT));
            float4 s1 = __ldg(reinterpret_cast<const float4*>(slots + (size_t)tokA * SLOT + 4));
            slA[0] = s0.x; slA[1] = s0.y; slA[2] = s0.z; slA[3] = s0.w;
            slA[4] = s1.x; slA[5] = s1.y; slA[6] = s1.z; slA[7] = s1.w;
            float4 t0 = __ldg(reinterpret_cast<const float4*>(slots + (size_t)tokB * SLOT));
            float4 t1 = __ldg(reinterpret_cast<const float4*>(slots + (size_t)tokB * SLOT + 4));
            slB[0] = t0.x; slB[1] = t0.y; slB[2] = t0.z; slB[3] = t0.w;
            slB[4] = t1.x; slB[5] = t1.y; slB[6] = t1.z; slB[7] = t1.w;
        }

        #pragma unroll 2
        for (int wi = 0; wi < RW / 8; wi++) {
            const int wl = wrp * 8 + wi;                 // local w index (warp-uniform)
            const float* wp = &s_wsel[wl * 96];

            float vA[NLEAF], vB[NLEAF];
            #pragma unroll
            for (int l = 0; l < NLEAF; l++) {
                float4 wv0 = *reinterpret_cast<const float4*>(wp + l * 12);
                float4 wv1 = *reinterpret_cast<const float4*>(wp + l * 12 + 4);
                float4 wv2 = *reinterpret_cast<const float4*>(wp + l * 12 + 8); // .x = bias
                float a = fmaf(wv0.x, slA[0], wv2.x);
                float b = fmaf(wv0.x, slB[0], wv2.x);
                a = fmaf(wv0.y, slA[1], a);  b = fmaf(wv0.y, slB[1], b);
                a = fmaf(wv0.z, slA[2], a);  b = fmaf(wv0.z, slB[2], b);
                a = fmaf(wv0.w, slA[3], a);  b = fmaf(wv0.w, slB[3], b);
                a = fmaf(wv1.x, slA[4], a);  b = fmaf(wv1.x, slB[4], b);
                a = fmaf(wv1.y, slA[5], a);  b = fmaf(wv1.y, slB[5], b);
                a = fmaf(wv1.z, slA[6], a);  b = fmaf(wv1.z, slB[6], b);
                a = fmaf(wv1.w, slA[7], a);  b = fmaf(wv1.w, slB[7], b);
                vA[l] = a;
                vB[l] = b;
            }

            // 3-level tree for both tokens (2 independent MUFU chains)
            #pragma unroll
            for (int n = 4; n >= 1; n >>= 1) {
                #pragma unroll
                for (int j = 0; j < 4; j++) {
                    if (j < n) {
                        float LA = vA[2 * j], RA = vA[2 * j + 1];
                        float LB = vB[2 * j], RB = vB[2 * j + 1];
                        float za = fmaf(pws, LA * RA, nbs);
                        float zb = fmaf(pws, LB * RB, nbs);
                        za = fmaf(a2, RA, za);   zb = fmaf(a2, RB, zb);
                        za = fmaf(a1, LA, za);   zb = fmaf(a1, LB, zb);
                        vA[j] = tanh_prescaled(za);
                        vB[j] = tanh_prescaled(zb);
                    }
                }
            }
            s_out[lane * ROW_H + wl]        = __float2half(vA[0]);
            s_out[(lane + 32) * ROW_H + wl] = __float2half(vB[0]);
        }
        __syncthreads();

        // flush: 64 rows x 64 halves (128B) coalesced.
        // Row byte stride = 132 (4B-aligned only) -> gather via 4x LDS.32.
        {
            const uint32_t* sp = reinterpret_cast<const uint32_t*>(s_out);
            #pragma unroll
            for (int f = 0; f < 2; f++) {
                int idx = tid + f * 256;             // 0..511
                int row = idx >> 3;                  // 0..63
                int seg = idx & 7;                   // 0..7 (x16 bytes)
                int e = row * 33 + seg * 4;          // word index (132B row = 33 words)
                uint4 val;
                val.x = sp[e + 0];
                val.y = sp[e + 1];
                val.z = sp[e + 2];
                val.w = sp[e + 3];
                *reinterpret_cast<uint4*>(A + (size_t)(tb0 + tt * 64 + row) * WDIM + w0 + seg * 8) = val;
            }
        }
        __syncthreads();
    }
}

// ---------------------------------------------------------------------------
// Kernel 3b: transpose out_w [K][N] fp32 -> B [N][K] fp16
// ---------------------------------------------------------------------------
__global__ __launch_bounds__(256)
void transpose_kernel(const float* __restrict__ W,
                      __half* __restrict__ B) {
    __shared__ float t[32][33];
    int tx = threadIdx.x, ty = threadIdx.y;       // block (32, 8)
    int k0 = blockIdx.x * 32, n0 = blockIdx.y * 32;

    #pragma unroll
    for (int i = 0; i < 4; i++)
        t[ty + 8 * i][tx] = W[(size_t)(k0 + ty + 8 * i) * DDIM + n0 + tx];
    __syncthreads();

    #pragma unroll
    for (int i = 0; i < 4; i++)
        B[(size_t)(n0 + ty + 8 * i) * WDIM + k0 + tx] = __float2half(t[tx][ty + 8 * i]);
}

// ---------------------------------------------------------------------------
// Kernel 4: mma.sync fp16 GEMM.  C[4096,1024] = A B^T + bias  (fp32 accum)
// CTA 128x256, K-chunk 64, 4-stage cp.async pipeline, 16 warps (4x4).
// ---------------------------------------------------------------------------
__global__ void __launch_bounds__(GT, 1)
gemm_mma_kernel(const __half* __restrict__ A,
                const __half* __restrict__ B,
                const float* __restrict__ bias,
                float* __restrict__ C) {
    extern __shared__ char smem[];
    const uint32_t sbase = smem_u32(smem);
    const int tid  = threadIdx.x;
    const int lane = tid & 31;
    const int w    = tid >> 5;        // 0..15
    const int wm   = w & 3;           // M warp coord (x32)
    const int wn   = w >> 2;          // N warp coord (x64)
    const int brow = blockIdx.y * TMM;
    const int bcol = blockIdx.x * TNN;
    const int K = WDIM;

    float acc[2][8][4];
    #pragma unroll
    for (int a = 0; a < 2; a++)
        #pragma unroll
        for (int b = 0; b < 8; b++)
            #pragma unroll
            for (int c = 0; c < 4; c++) acc[a][b][c] = 0.0f;

    // ldmatrix lane->address precomputation
    const int lr   = lane & 7;
    const int ls8  = (lane >> 3) & 1;       // A: +8 rows    B: +1 k-chunk
    const int lhi  = lane >> 4;             // A: +1 k-chunk B: +8 rows
    const int arow0 = wm * 32 + lr + ls8 * 8;
    const int brow0 = wn * 64 + lr + lhi * 8;
    const uint32_t aswz = arow0 & 7;
    const uint32_t bswz = brow0 & 7;
    uint32_t arowb[2], browb[4];
    #pragma unroll
    for (int mt = 0; mt < 2; mt++) arowb[mt] = (uint32_t)(arow0 + mt * 16) << 7;
    #pragma unroll
    for (int i = 0; i < 4; i++)    browb[i] = (uint32_t)(brow0 + i * 16) << 7;

    // stage loader: A rows (brow..+127), B rows (bcol..+255), k0..k0+63
    auto load_stage = [&](int ci) {
        const uint32_t sb = sbase + (ci % NSTG) * STAGE;
        const int k0 = ci * KCC;
        #pragma unroll
        for (int it = 0; it < 2; it++) {
            int idx = tid + it * GT;          // 0..1023
            int r = idx >> 3, c = idx & 7;
            uint32_t sw = ((uint32_t)r << 7) + (((uint32_t)(c ^ (r & 7))) << 4);
            cp16(sb + OFF_A + sw, A + (size_t)(brow + r) * K + k0 + c * 8);
        }
        #pragma unroll
        for (int it = 0; it < 4; it++) {
            int idx = tid + it * GT;          // 0..2047
            int r = idx >> 3, c = idx & 7;
            uint32_t sw = ((uint32_t)r << 7) + (((uint32_t)(c ^ (r & 7))) << 4);
            cp16(sb + OFF_B + sw, B + (size_t)(bcol + r) * K + k0 + c * 8);
        }
    };

    load_stage(0); CP_COMMIT();
    load_stage(1); CP_COMMIT();
    load_stage(2); CP_COMMIT();

    for (int i = 0; i < NCH; i++) {
        CP_WAIT(2);            // stage i landed (this thread's view)
        __syncthreads();       // visible to all; all warps done with stage i-1

        if (i + 3 < NCH) { load_stage(i + 3); CP_COMMIT(); }

        const uint32_t sb = sbase + (i % NSTG) * STAGE;
        #pragma unroll
        for (int s = 0; s < 4; s++) {
            uint32_t ach = (((uint32_t)(2 * s + lhi)) ^ aswz) << 4;
            uint32_t bch = (((uint32_t)(2 * s + ls8)) ^ bswz) << 4;
            uint32_t af[2][4], bf[4][4];
            #pragma unroll
            for (int mt = 0; mt < 2; mt++)
                ldsm_x4(af[mt], sb + OFF_A + arowb[mt] + ach);
            #pragma unroll
            for (int bt = 0; bt < 4; bt++)
                ldsm_x4(bf[bt], sb + OFF_B + browb[bt] + bch);
            #pragma unroll
            for (int mt = 0; mt < 2; mt++)
                #pragma unroll
                for (int bt = 0; bt < 4; bt++) {
                    mma_fp16(acc[mt][2 * bt + 0], af[mt], bf[bt][0], bf[bt][1]);
                    mma_fp16(acc[mt][2 * bt + 1], af[mt], bf[bt][2], bf[bt][3]);
                }
        }
    }

    // Epilogue: acc -> C + bias
    const int r0 = lane >> 2;
    const int c0 = (lane & 3) * 2;
    #pragma unroll
    for (int mt = 0; mt < 2; mt++) {
        int grow = brow + wm * 32 + mt * 16 + r0;
        #pragma unroll
        for (int half = 0; half < 2; half++) {
            float* crow = C + (size_t)(grow + half * 8) * DDIM;
            #pragma unroll
            for (int nt = 0; nt < 8; nt++) {
                int gc = bcol + wn * 64 + nt * 8 + c0;
                float2 o;
                o.x = acc[mt][nt][half * 2 + 0] + bias[gc];
                o.y = acc[mt][nt][half * 2 + 1] + bias[gc + 1];
                *reinterpret_cast<float2*>(crow + gc) = o;
            }
        }
    }
}

// ---------------------------------------------------------------------------
// Launch.  Inputs: hidden, slot_w, slot_b, leaf_logits, node_params, out_w, out_b
// ---------------------------------------------------------------------------
extern "C" void kernel_launch(void* const* d_in, const int* in_sizes, int n_in,
                              void* d_out, int out_size) {
    const float* hidden      = (const float*)d_in[0];
    const float* slot_w      = (const float*)d_in[1];
    const float* slot_b      = (const float*)d_in[2];
    const float* leaf_logits = (const float*)d_in[3];
    const float* node_params = (const float*)d_in[4];
    const float* out_w       = (const float*)d_in[5];
    const float* out_b       = (const float*)d_in[6];
    float* out = (float*)d_out;

    float* wsel;  cudaGetSymbolAddress((void**)&wsel,  g_wsel);
    float* slots; cudaGetSymbolAddress((void**)&slots, g_slots);
    __half *A, *B;
    cudaGetSymbolAddress((void**)&A, g_a);
    cudaGetSymbolAddress((void**)&B, g_b);

    cudaFuncSetAttribute(gemm_mma_kernel,
                         cudaFuncAttributeMaxDynamicSharedMemorySize, GSMEM);

    // 1) selector softmax + constant folding (12-padded)
    prep_selector_kernel<<<(WDIM * NLEAF + 255) / 256, 256>>>(leaf_logits, wsel);

    // 2) slots
    slots_kernel<<<(NTOK * 32 + 255) / 256, 256>>>(hidden, slot_w, slot_b, slots);

    // 3b) transpose out_w -> fp16 [N][K]
    {
        dim3 grid(WDIM / 32, DDIM / 32);
        transpose_kernel<<<grid, dim3(32, 8)>>>(out_w, B);
    }

    // 3) roots -> fp16 [M][K]
    {
        dim3 grid(WDIM / RW, NTOK / RT);
        roots_kernel<<<grid, 256>>>(wsel, slots, node_params, A);
    }

    // 4) tensor-core GEMM + bias
    {
        dim3 grid(DDIM / TNN, NTOK / TMM);
        gemm_mma_kernel<<<grid, GT, GSMEM>>>(A, B, out_b, out);
    }
}